// round 4
// baseline (speedup 1.0000x reference)
#include <cuda_runtime.h>

#define SH_C0 0.28209479177387814f
#define SH_C1 0.4886025119029199f

__device__ __forceinline__ float sigmoidf(float v) {
    return 1.0f / (1.0f + expf(-v));
}

__global__ void __launch_bounds__(256) gaussian_kernel(
    const float* __restrict__ view_dirs,   // (N,3)
    const float* __restrict__ xyz,         // (N,3)
    const float* __restrict__ scale_log,   // (N,3)
    const float* __restrict__ rot_quat,    // (N,4)
    const float* __restrict__ opacity_logit, // (N,1)
    const float* __restrict__ sh_coeffs,   // (N,3,4)
    float* __restrict__ out,               // [xyz(3N) | cov3d(9N) | rgb(3N) | opacity(N)]
    int n)
{
    int i = blockIdx.x * blockDim.x + threadIdx.x;
    if (i >= n) return;

    // ---- loads ----
    float dx = view_dirs[3 * i + 0];
    float dy = view_dirs[3 * i + 1];
    float dz = view_dirs[3 * i + 2];

    float px = xyz[3 * i + 0];
    float py = xyz[3 * i + 1];
    float pz = xyz[3 * i + 2];

    float sl0 = scale_log[3 * i + 0];
    float sl1 = scale_log[3 * i + 1];
    float sl2 = scale_log[3 * i + 2];

    float4 q  = reinterpret_cast<const float4*>(rot_quat)[i];
    float4 c0 = reinterpret_cast<const float4*>(sh_coeffs)[3 * i + 0];
    float4 c1 = reinterpret_cast<const float4*>(sh_coeffs)[3 * i + 1];
    float4 c2 = reinterpret_cast<const float4*>(sh_coeffs)[3 * i + 2];

    float opl = opacity_logit[i];

    // ---- math ----
    float opac = sigmoidf(opl);

    float s0 = expf(sl0);
    float s1 = expf(sl1);
    float s2 = expf(sl2);

    // SH degree-1 eval, then sigmoid
    float rr = SH_C0 * c0.x - SH_C1 * dy * c0.y + SH_C1 * dz * c0.z - SH_C1 * dx * c0.w;
    float rg = SH_C0 * c1.x - SH_C1 * dy * c1.y + SH_C1 * dz * c1.z - SH_C1 * dx * c1.w;
    float rb = SH_C0 * c2.x - SH_C1 * dy * c2.y + SH_C1 * dz * c2.z - SH_C1 * dx * c2.w;
    rr = sigmoidf(rr);
    rg = sigmoidf(rg);
    rb = sigmoidf(rb);

    // quaternion -> rotation
    float nrm = sqrtf(q.x * q.x + q.y * q.y + q.z * q.z + q.w * q.w);
    float inv = 1.0f / fmaxf(nrm, 1e-12f);
    float r = q.x * inv, x = q.y * inv, y = q.z * inv, z = q.w * inv;

    float R00 = 1.0f - 2.0f * (y * y + z * z);
    float R01 = 2.0f * (x * y - r * z);
    float R02 = 2.0f * (x * z + r * y);
    float R10 = 2.0f * (x * y + r * z);
    float R11 = 1.0f - 2.0f * (x * x + z * z);
    float R12 = 2.0f * (y * z - r * x);
    float R20 = 2.0f * (x * z - r * y);
    float R21 = 2.0f * (y * z + r * x);
    float R22 = 1.0f - 2.0f * (x * x + y * y);

    // M = R * diag(scale) (scale applies per column); cov = M M^T
    float M00 = R00 * s0, M01 = R01 * s1, M02 = R02 * s2;
    float M10 = R10 * s0, M11 = R11 * s1, M12 = R12 * s2;
    float M20 = R20 * s0, M21 = R21 * s1, M22 = R22 * s2;

    float cov00 = M00 * M00 + M01 * M01 + M02 * M02;
    float cov01 = M00 * M10 + M01 * M11 + M02 * M12;
    float cov02 = M00 * M20 + M01 * M21 + M02 * M22;
    float cov11 = M10 * M10 + M11 * M11 + M12 * M12;
    float cov12 = M10 * M20 + M11 * M21 + M12 * M22;
    float cov22 = M20 * M20 + M21 * M21 + M22 * M22;

    // ---- stores ----
    float* o_xyz = out;
    float* o_cov = out + 3LL * n;
    float* o_rgb = out + 12LL * n;
    float* o_op  = out + 15LL * n;

    o_xyz[3 * i + 0] = px;
    o_xyz[3 * i + 1] = py;
    o_xyz[3 * i + 2] = pz;

    o_cov[9 * i + 0] = cov00;
    o_cov[9 * i + 1] = cov01;
    o_cov[9 * i + 2] = cov02;
    o_cov[9 * i + 3] = cov01;
    o_cov[9 * i + 4] = cov11;
    o_cov[9 * i + 5] = cov12;
    o_cov[9 * i + 6] = cov02;
    o_cov[9 * i + 7] = cov12;
    o_cov[9 * i + 8] = cov22;

    o_rgb[3 * i + 0] = rr;
    o_rgb[3 * i + 1] = rg;
    o_rgb[3 * i + 2] = rb;

    o_op[i] = opac;
}

extern "C" void kernel_launch(void* const* d_in, const int* in_sizes, int n_in,
                              void* d_out, int out_size) {
    const float* view_dirs     = (const float*)d_in[0];
    const float* xyz           = (const float*)d_in[1];
    const float* scale_log     = (const float*)d_in[2];
    const float* rot_quat      = (const float*)d_in[3];
    const float* opacity_logit = (const float*)d_in[4];
    const float* sh_coeffs     = (const float*)d_in[5];
    float* out = (float*)d_out;

    int n = in_sizes[0] / 3;  // view_dirs has N*3 elements

    int threads = 256;
    int blocks = (n + threads - 1) / threads;
    gaussian_kernel<<<blocks, threads>>>(view_dirs, xyz, scale_log, rot_quat,
                                         opacity_logit, sh_coeffs, out, n);
}

// round 9
// speedup vs baseline: 2.1428x; 2.1428x over previous
#include <cuda_runtime.h>

#define SH_C0 0.28209479177387814f
#define SH_C1 0.4886025119029199f

#define NPB 256  // points per block (== threads per block)

__device__ __forceinline__ float sigmoidf(float v) {
    return 1.0f / (1.0f + expf(-v));
}

// Core per-point math: inputs -> outputs (all in registers).
__device__ __forceinline__ void gauss_math(
    float dx, float dy, float dz,
    float sl0, float sl1, float sl2,
    float qr, float qx, float qy, float qz,
    float opl,
    const float4& c0, const float4& c1, const float4& c2,
    float& rr, float& rg, float& rb, float& opac,
    float& cov00, float& cov01, float& cov02,
    float& cov11, float& cov12, float& cov22)
{
    opac = sigmoidf(opl);

    float s0 = expf(sl0);
    float s1 = expf(sl1);
    float s2 = expf(sl2);

    rr = SH_C0 * c0.x - SH_C1 * dy * c0.y + SH_C1 * dz * c0.z - SH_C1 * dx * c0.w;
    rg = SH_C0 * c1.x - SH_C1 * dy * c1.y + SH_C1 * dz * c1.z - SH_C1 * dx * c1.w;
    rb = SH_C0 * c2.x - SH_C1 * dy * c2.y + SH_C1 * dz * c2.z - SH_C1 * dx * c2.w;
    rr = sigmoidf(rr);
    rg = sigmoidf(rg);
    rb = sigmoidf(rb);

    float nrm = sqrtf(qr * qr + qx * qx + qy * qy + qz * qz);
    float inv = 1.0f / fmaxf(nrm, 1e-12f);
    float r = qr * inv, x = qx * inv, y = qy * inv, z = qz * inv;

    float R00 = 1.0f - 2.0f * (y * y + z * z);
    float R01 = 2.0f * (x * y - r * z);
    float R02 = 2.0f * (x * z + r * y);
    float R10 = 2.0f * (x * y + r * z);
    float R11 = 1.0f - 2.0f * (x * x + z * z);
    float R12 = 2.0f * (y * z - r * x);
    float R20 = 2.0f * (x * z - r * y);
    float R21 = 2.0f * (y * z + r * x);
    float R22 = 1.0f - 2.0f * (x * x + y * y);

    float M00 = R00 * s0, M01 = R01 * s1, M02 = R02 * s2;
    float M10 = R10 * s0, M11 = R11 * s1, M12 = R12 * s2;
    float M20 = R20 * s0, M21 = R21 * s1, M22 = R22 * s2;

    cov00 = M00 * M00 + M01 * M01 + M02 * M02;
    cov01 = M00 * M10 + M01 * M11 + M02 * M12;
    cov02 = M00 * M20 + M01 * M21 + M02 * M22;
    cov11 = M10 * M10 + M11 * M11 + M12 * M12;
    cov12 = M10 * M20 + M11 * M21 + M12 * M22;
    cov22 = M20 * M20 + M21 * M21 + M22 * M22;
}

// Vectorized kernel: smem transpose so every global access is a coalesced float4.
// Requires: grid covers full blocks only (n_full * NPB points), n % 4 == 0.
__global__ void __launch_bounds__(NPB) gaussian_kernel_vec(
    const float* __restrict__ view_dirs,
    const float* __restrict__ xyz,
    const float* __restrict__ scale_log,
    const float* __restrict__ rot_quat,
    const float* __restrict__ opacity_logit,
    const float* __restrict__ sh_coeffs,
    float* __restrict__ out,
    int n)
{
    // float offsets inside smem (inputs):
    //   VD 0..768, XYZ 768..1536, SL 1536..2304, Q 2304..3328, OP 3328..3584, SH 3584..6656
    // outputs (reused after sync):
    //   OXYZ 0..768, OCOV 768..3072, ORGB 3072..3840, OOP 3840..4096
    __shared__ float s[6656];
    float4* s4 = reinterpret_cast<float4*>(s);

    const int tid = threadIdx.x;
    const size_t b = blockIdx.x;

    // ---- stage inputs: perfectly coalesced float4 copies ----
    const float4* vd4 = reinterpret_cast<const float4*>(view_dirs)     + b * 192;
    const float4* xy4 = reinterpret_cast<const float4*>(xyz)           + b * 192;
    const float4* sl4 = reinterpret_cast<const float4*>(scale_log)     + b * 192;
    const float4* q4  = reinterpret_cast<const float4*>(rot_quat)      + b * 256;
    const float4* op4 = reinterpret_cast<const float4*>(opacity_logit) + b * 64;
    const float4* sh4 = reinterpret_cast<const float4*>(sh_coeffs)     + b * 768;

    if (tid < 192) {
        s4[0   + tid] = vd4[tid];
        s4[192 + tid] = xy4[tid];
        s4[384 + tid] = sl4[tid];
    }
    s4[576 + tid] = q4[tid];
    if (tid < 64) s4[832 + tid] = op4[tid];
    s4[896 + tid]       = sh4[tid];
    s4[896 + 256 + tid] = sh4[256 + tid];
    s4[896 + 512 + tid] = sh4[512 + tid];
    __syncthreads();

    // ---- read this thread's point from smem (conflict-free strides) ----
    const int p = tid;
    float dx  = s[3 * p + 0],      dy  = s[3 * p + 1],       dz  = s[3 * p + 2];
    float px  = s[768 + 3 * p],    py  = s[768 + 3 * p + 1],  pz  = s[768 + 3 * p + 2];
    float sl0 = s[1536 + 3 * p],   sl1 = s[1536 + 3 * p + 1], sl2 = s[1536 + 3 * p + 2];
    float4 q  = reinterpret_cast<const float4*>(s + 2304)[p];
    float opl = s[3328 + p];
    float4 c0 = reinterpret_cast<const float4*>(s + 3584)[3 * p + 0];
    float4 c1 = reinterpret_cast<const float4*>(s + 3584)[3 * p + 1];
    float4 c2 = reinterpret_cast<const float4*>(s + 3584)[3 * p + 2];

    float rr, rg, rb, opac, cov00, cov01, cov02, cov11, cov12, cov22;
    gauss_math(dx, dy, dz, sl0, sl1, sl2, q.x, q.y, q.z, q.w, opl,
               c0, c1, c2, rr, rg, rb, opac,
               cov00, cov01, cov02, cov11, cov12, cov22);

    __syncthreads();  // all input reads done before output overwrites

    // ---- write outputs to smem (strides 3, 9, 1: conflict-free) ----
    s[3 * p + 0] = px;  s[3 * p + 1] = py;  s[3 * p + 2] = pz;

    float* sc = s + 768 + 9 * p;
    sc[0] = cov00; sc[1] = cov01; sc[2] = cov02;
    sc[3] = cov01; sc[4] = cov11; sc[5] = cov12;
    sc[6] = cov02; sc[7] = cov12; sc[8] = cov22;

    s[3072 + 3 * p + 0] = rr; s[3072 + 3 * p + 1] = rg; s[3072 + 3 * p + 2] = rb;
    s[3840 + p] = opac;
    __syncthreads();

    // ---- flush: coalesced float4 stores ----
    float4* oxyz4 = reinterpret_cast<float4*>(out)             + b * 192;
    float4* ocov4 = reinterpret_cast<float4*>(out + 3LL * n)   + b * 576;
    float4* orgb4 = reinterpret_cast<float4*>(out + 12LL * n)  + b * 192;
    float4* oop4  = reinterpret_cast<float4*>(out + 15LL * n)  + b * 64;

    if (tid < 192) {
        oxyz4[tid] = s4[tid];
        orgb4[tid] = s4[768 + tid];
    }
    ocov4[tid]       = s4[192 + tid];
    ocov4[256 + tid] = s4[448 + tid];
    if (tid < 64) {
        ocov4[512 + tid] = s4[704 + tid];
        oop4[tid]        = s4[960 + tid];
    }
}

// Scalar fallback / tail kernel: handles points [start, n).
__global__ void __launch_bounds__(256) gaussian_kernel_scalar(
    const float* __restrict__ view_dirs,
    const float* __restrict__ xyz,
    const float* __restrict__ scale_log,
    const float* __restrict__ rot_quat,
    const float* __restrict__ opacity_logit,
    const float* __restrict__ sh_coeffs,
    float* __restrict__ out,
    int start, int n)
{
    int i = start + blockIdx.x * blockDim.x + threadIdx.x;
    if (i >= n) return;

    float dx = view_dirs[3 * i + 0], dy = view_dirs[3 * i + 1], dz = view_dirs[3 * i + 2];
    float px = xyz[3 * i + 0], py = xyz[3 * i + 1], pz = xyz[3 * i + 2];
    float sl0 = scale_log[3 * i + 0], sl1 = scale_log[3 * i + 1], sl2 = scale_log[3 * i + 2];
    float4 q  = reinterpret_cast<const float4*>(rot_quat)[i];
    float opl = opacity_logit[i];
    float4 c0 = reinterpret_cast<const float4*>(sh_coeffs)[3 * i + 0];
    float4 c1 = reinterpret_cast<const float4*>(sh_coeffs)[3 * i + 1];
    float4 c2 = reinterpret_cast<const float4*>(sh_coeffs)[3 * i + 2];

    float rr, rg, rb, opac, cov00, cov01, cov02, cov11, cov12, cov22;
    gauss_math(dx, dy, dz, sl0, sl1, sl2, q.x, q.y, q.z, q.w, opl,
               c0, c1, c2, rr, rg, rb, opac,
               cov00, cov01, cov02, cov11, cov12, cov22);

    float* o_xyz = out;
    float* o_cov = out + 3LL * n;
    float* o_rgb = out + 12LL * n;
    float* o_op  = out + 15LL * n;

    o_xyz[3 * i + 0] = px; o_xyz[3 * i + 1] = py; o_xyz[3 * i + 2] = pz;

    o_cov[9 * i + 0] = cov00; o_cov[9 * i + 1] = cov01; o_cov[9 * i + 2] = cov02;
    o_cov[9 * i + 3] = cov01; o_cov[9 * i + 4] = cov11; o_cov[9 * i + 5] = cov12;
    o_cov[9 * i + 6] = cov02; o_cov[9 * i + 7] = cov12; o_cov[9 * i + 8] = cov22;

    o_rgb[3 * i + 0] = rr; o_rgb[3 * i + 1] = rg; o_rgb[3 * i + 2] = rb;
    o_op[i] = opac;
}

extern "C" void kernel_launch(void* const* d_in, const int* in_sizes, int n_in,
                              void* d_out, int out_size) {
    const float* view_dirs     = (const float*)d_in[0];
    const float* xyz           = (const float*)d_in[1];
    const float* scale_log     = (const float*)d_in[2];
    const float* rot_quat      = (const float*)d_in[3];
    const float* opacity_logit = (const float*)d_in[4];
    const float* sh_coeffs     = (const float*)d_in[5];
    float* out = (float*)d_out;

    int n = in_sizes[0] / 3;

    if ((n & 3) != 0) {
        // output-region float4 alignment would break; scalar path for everything
        int threads = 256;
        int blocks = (n + threads - 1) / threads;
        gaussian_kernel_scalar<<<blocks, threads>>>(view_dirs, xyz, scale_log, rot_quat,
                                                    opacity_logit, sh_coeffs, out, 0, n);
        return;
    }

    int full_blocks = n / NPB;
    int start_tail  = full_blocks * NPB;

    if (full_blocks > 0) {
        gaussian_kernel_vec<<<full_blocks, NPB>>>(view_dirs, xyz, scale_log, rot_quat,
                                                  opacity_logit, sh_coeffs, out, n);
    }
    if (start_tail < n) {
        int rem = n - start_tail;
        int blocks = (rem + 255) / 256;
        gaussian_kernel_scalar<<<blocks, 256>>>(view_dirs, xyz, scale_log, rot_quat,
                                                opacity_logit, sh_coeffs, out, start_tail, n);
    }
}

// round 10
// speedup vs baseline: 2.2347x; 1.0429x over previous
#include <cuda_runtime.h>

#define SH_C0 0.28209479177387814f
#define SH_C1 0.4886025119029199f

#define NPB 256  // points per block (== threads per block)

__device__ __forceinline__ float sigmoidf(float v) {
    return 1.0f / (1.0f + expf(-v));
}

// Core per-point math: inputs -> outputs (all in registers).
__device__ __forceinline__ void gauss_math(
    float dx, float dy, float dz,
    float sl0, float sl1, float sl2,
    float qr, float qx, float qy, float qz,
    float opl,
    const float4& c0, const float4& c1, const float4& c2,
    float& rr, float& rg, float& rb, float& opac,
    float& cov00, float& cov01, float& cov02,
    float& cov11, float& cov12, float& cov22)
{
    opac = sigmoidf(opl);

    float s0 = expf(sl0);
    float s1 = expf(sl1);
    float s2 = expf(sl2);

    rr = SH_C0 * c0.x - SH_C1 * dy * c0.y + SH_C1 * dz * c0.z - SH_C1 * dx * c0.w;
    rg = SH_C0 * c1.x - SH_C1 * dy * c1.y + SH_C1 * dz * c1.z - SH_C1 * dx * c1.w;
    rb = SH_C0 * c2.x - SH_C1 * dy * c2.y + SH_C1 * dz * c2.z - SH_C1 * dx * c2.w;
    rr = sigmoidf(rr);
    rg = sigmoidf(rg);
    rb = sigmoidf(rb);

    float nrm = sqrtf(qr * qr + qx * qx + qy * qy + qz * qz);
    float inv = 1.0f / fmaxf(nrm, 1e-12f);
    float r = qr * inv, x = qx * inv, y = qy * inv, z = qz * inv;

    float R00 = 1.0f - 2.0f * (y * y + z * z);
    float R01 = 2.0f * (x * y - r * z);
    float R02 = 2.0f * (x * z + r * y);
    float R10 = 2.0f * (x * y + r * z);
    float R11 = 1.0f - 2.0f * (x * x + z * z);
    float R12 = 2.0f * (y * z - r * x);
    float R20 = 2.0f * (x * z - r * y);
    float R21 = 2.0f * (y * z + r * x);
    float R22 = 1.0f - 2.0f * (x * x + y * y);

    float M00 = R00 * s0, M01 = R01 * s1, M02 = R02 * s2;
    float M10 = R10 * s0, M11 = R11 * s1, M12 = R12 * s2;
    float M20 = R20 * s0, M21 = R21 * s1, M22 = R22 * s2;

    cov00 = M00 * M00 + M01 * M01 + M02 * M02;
    cov01 = M00 * M10 + M01 * M11 + M02 * M12;
    cov02 = M00 * M20 + M01 * M21 + M02 * M22;
    cov11 = M10 * M10 + M11 * M11 + M12 * M12;
    cov12 = M10 * M20 + M11 * M21 + M12 * M22;
    cov22 = M20 * M20 + M21 * M21 + M22 * M22;
}

// Scalar per-point path (used by the partial last block and the n%4!=0 fallback).
__device__ __forceinline__ void gauss_point_scalar(
    const float* __restrict__ view_dirs,
    const float* __restrict__ xyz,
    const float* __restrict__ scale_log,
    const float* __restrict__ rot_quat,
    const float* __restrict__ opacity_logit,
    const float* __restrict__ sh_coeffs,
    float* __restrict__ out,
    int i, int n)
{
    float dx = view_dirs[3 * i + 0], dy = view_dirs[3 * i + 1], dz = view_dirs[3 * i + 2];
    float px = xyz[3 * i + 0], py = xyz[3 * i + 1], pz = xyz[3 * i + 2];
    float sl0 = scale_log[3 * i + 0], sl1 = scale_log[3 * i + 1], sl2 = scale_log[3 * i + 2];
    float4 q  = reinterpret_cast<const float4*>(rot_quat)[i];
    float opl = opacity_logit[i];
    float4 c0 = reinterpret_cast<const float4*>(sh_coeffs)[3 * i + 0];
    float4 c1 = reinterpret_cast<const float4*>(sh_coeffs)[3 * i + 1];
    float4 c2 = reinterpret_cast<const float4*>(sh_coeffs)[3 * i + 2];

    float rr, rg, rb, opac, cov00, cov01, cov02, cov11, cov12, cov22;
    gauss_math(dx, dy, dz, sl0, sl1, sl2, q.x, q.y, q.z, q.w, opl,
               c0, c1, c2, rr, rg, rb, opac,
               cov00, cov01, cov02, cov11, cov12, cov22);

    float* o_xyz = out;
    float* o_cov = out + 3LL * n;
    float* o_rgb = out + 12LL * n;
    float* o_op  = out + 15LL * n;

    o_xyz[3 * i + 0] = px; o_xyz[3 * i + 1] = py; o_xyz[3 * i + 2] = pz;

    o_cov[9 * i + 0] = cov00; o_cov[9 * i + 1] = cov01; o_cov[9 * i + 2] = cov02;
    o_cov[9 * i + 3] = cov01; o_cov[9 * i + 4] = cov11; o_cov[9 * i + 5] = cov12;
    o_cov[9 * i + 6] = cov02; o_cov[9 * i + 7] = cov12; o_cov[9 * i + 8] = cov22;

    o_rgb[3 * i + 0] = rr; o_rgb[3 * i + 1] = rg; o_rgb[3 * i + 2] = rb;
    o_op[i] = opac;
}

// Merged kernel: full blocks run the smem-transpose float4 path; the single
// partial last block (if any) runs the guarded scalar path. One launch, no
// serialized tail. Requires n % 4 == 0 for the vec path's float4 output bases.
__global__ void __launch_bounds__(NPB) gaussian_kernel_fused(
    const float* __restrict__ view_dirs,
    const float* __restrict__ xyz,
    const float* __restrict__ scale_log,
    const float* __restrict__ rot_quat,
    const float* __restrict__ opacity_logit,
    const float* __restrict__ sh_coeffs,
    float* __restrict__ out,
    int n, int n_full_blocks)
{
    __shared__ float s[6656];
    float4* s4 = reinterpret_cast<float4*>(s);

    const int tid = threadIdx.x;
    const size_t b = blockIdx.x;

    if (blockIdx.x >= n_full_blocks) {
        // ---- partial tail block: guarded scalar path ----
        int i = blockIdx.x * NPB + tid;
        if (i < n) {
            gauss_point_scalar(view_dirs, xyz, scale_log, rot_quat,
                               opacity_logit, sh_coeffs, out, i, n);
        }
        return;
    }

    // ---- stage inputs: perfectly coalesced float4 copies ----
    const float4* vd4 = reinterpret_cast<const float4*>(view_dirs)     + b * 192;
    const float4* xy4 = reinterpret_cast<const float4*>(xyz)           + b * 192;
    const float4* sl4 = reinterpret_cast<const float4*>(scale_log)     + b * 192;
    const float4* q4  = reinterpret_cast<const float4*>(rot_quat)      + b * 256;
    const float4* op4 = reinterpret_cast<const float4*>(opacity_logit) + b * 64;
    const float4* sh4 = reinterpret_cast<const float4*>(sh_coeffs)     + b * 768;

    if (tid < 192) {
        s4[0   + tid] = vd4[tid];
        s4[192 + tid] = xy4[tid];
        s4[384 + tid] = sl4[tid];
    }
    s4[576 + tid] = q4[tid];
    if (tid < 64) s4[832 + tid] = op4[tid];
    s4[896 + tid]       = sh4[tid];
    s4[896 + 256 + tid] = sh4[256 + tid];
    s4[896 + 512 + tid] = sh4[512 + tid];
    __syncthreads();

    // ---- read this thread's point from smem (conflict-free strides) ----
    const int p = tid;
    float dx  = s[3 * p + 0],      dy  = s[3 * p + 1],       dz  = s[3 * p + 2];
    float px  = s[768 + 3 * p],    py  = s[768 + 3 * p + 1],  pz  = s[768 + 3 * p + 2];
    float sl0 = s[1536 + 3 * p],   sl1 = s[1536 + 3 * p + 1], sl2 = s[1536 + 3 * p + 2];
    float4 q  = reinterpret_cast<const float4*>(s + 2304)[p];
    float opl = s[3328 + p];
    float4 c0 = reinterpret_cast<const float4*>(s + 3584)[3 * p + 0];
    float4 c1 = reinterpret_cast<const float4*>(s + 3584)[3 * p + 1];
    float4 c2 = reinterpret_cast<const float4*>(s + 3584)[3 * p + 2];

    float rr, rg, rb, opac, cov00, cov01, cov02, cov11, cov12, cov22;
    gauss_math(dx, dy, dz, sl0, sl1, sl2, q.x, q.y, q.z, q.w, opl,
               c0, c1, c2, rr, rg, rb, opac,
               cov00, cov01, cov02, cov11, cov12, cov22);

    __syncthreads();  // all input reads done before output overwrites

    // ---- write outputs to smem (strides 3, 9, 1: conflict-free) ----
    s[3 * p + 0] = px;  s[3 * p + 1] = py;  s[3 * p + 2] = pz;

    float* sc = s + 768 + 9 * p;
    sc[0] = cov00; sc[1] = cov01; sc[2] = cov02;
    sc[3] = cov01; sc[4] = cov11; sc[5] = cov12;
    sc[6] = cov02; sc[7] = cov12; sc[8] = cov22;

    s[3072 + 3 * p + 0] = rr; s[3072 + 3 * p + 1] = rg; s[3072 + 3 * p + 2] = rb;
    s[3840 + p] = opac;
    __syncthreads();

    // ---- flush: coalesced float4 stores ----
    float4* oxyz4 = reinterpret_cast<float4*>(out)             + b * 192;
    float4* ocov4 = reinterpret_cast<float4*>(out + 3LL * n)   + b * 576;
    float4* orgb4 = reinterpret_cast<float4*>(out + 12LL * n)  + b * 192;
    float4* oop4  = reinterpret_cast<float4*>(out + 15LL * n)  + b * 64;

    if (tid < 192) {
        oxyz4[tid] = s4[tid];
        orgb4[tid] = s4[768 + tid];
    }
    ocov4[tid]       = s4[192 + tid];
    ocov4[256 + tid] = s4[448 + tid];
    if (tid < 64) {
        ocov4[512 + tid] = s4[704 + tid];
        oop4[tid]        = s4[960 + tid];
    }
}

// Pure scalar kernel for the n % 4 != 0 fallback (output float4 bases unaligned).
__global__ void __launch_bounds__(256) gaussian_kernel_scalar(
    const float* __restrict__ view_dirs,
    const float* __restrict__ xyz,
    const float* __restrict__ scale_log,
    const float* __restrict__ rot_quat,
    const float* __restrict__ opacity_logit,
    const float* __restrict__ sh_coeffs,
    float* __restrict__ out,
    int n)
{
    int i = blockIdx.x * blockDim.x + threadIdx.x;
    if (i >= n) return;
    gauss_point_scalar(view_dirs, xyz, scale_log, rot_quat,
                       opacity_logit, sh_coeffs, out, i, n);
}

extern "C" void kernel_launch(void* const* d_in, const int* in_sizes, int n_in,
                              void* d_out, int out_size) {
    const float* view_dirs     = (const float*)d_in[0];
    const float* xyz           = (const float*)d_in[1];
    const float* scale_log     = (const float*)d_in[2];
    const float* rot_quat      = (const float*)d_in[3];
    const float* opacity_logit = (const float*)d_in[4];
    const float* sh_coeffs     = (const float*)d_in[5];
    float* out = (float*)d_out;

    int n = in_sizes[0] / 3;

    if ((n & 3) != 0) {
        // output-region float4 alignment would break; scalar path for everything
        int threads = 256;
        int blocks = (n + threads - 1) / threads;
        gaussian_kernel_scalar<<<blocks, threads>>>(view_dirs, xyz, scale_log, rot_quat,
                                                    opacity_logit, sh_coeffs, out, n);
        return;
    }

    int n_full_blocks = n / NPB;
    int grid = (n + NPB - 1) / NPB;  // full blocks + at most one partial block

    gaussian_kernel_fused<<<grid, NPB>>>(view_dirs, xyz, scale_log, rot_quat,
                                         opacity_logit, sh_coeffs, out,
                                         n, n_full_blocks);
}

// round 12
// speedup vs baseline: 2.2481x; 1.0060x over previous
#include <cuda_runtime.h>

#define SH_C0 0.28209479177387814f
#define SH_C1 0.4886025119029199f

#define NPB 256  // points per block (== threads per block)

__device__ __forceinline__ float sigmoidf(float v) {
    return 1.0f / (1.0f + expf(-v));
}

// Core per-point math (xyz passthrough removed — handled as raw copy).
__device__ __forceinline__ void gauss_math(
    float dx, float dy, float dz,
    float sl0, float sl1, float sl2,
    float qr, float qx, float qy, float qz,
    float opl,
    const float4& c0, const float4& c1, const float4& c2,
    float& rr, float& rg, float& rb, float& opac,
    float& cov00, float& cov01, float& cov02,
    float& cov11, float& cov12, float& cov22)
{
    opac = sigmoidf(opl);

    float s0 = expf(sl0);
    float s1 = expf(sl1);
    float s2 = expf(sl2);

    rr = SH_C0 * c0.x - SH_C1 * dy * c0.y + SH_C1 * dz * c0.z - SH_C1 * dx * c0.w;
    rg = SH_C0 * c1.x - SH_C1 * dy * c1.y + SH_C1 * dz * c1.z - SH_C1 * dx * c1.w;
    rb = SH_C0 * c2.x - SH_C1 * dy * c2.y + SH_C1 * dz * c2.z - SH_C1 * dx * c2.w;
    rr = sigmoidf(rr);
    rg = sigmoidf(rg);
    rb = sigmoidf(rb);

    float nrm = sqrtf(qr * qr + qx * qx + qy * qy + qz * qz);
    float inv = 1.0f / fmaxf(nrm, 1e-12f);
    float r = qr * inv, x = qx * inv, y = qy * inv, z = qz * inv;

    float R00 = 1.0f - 2.0f * (y * y + z * z);
    float R01 = 2.0f * (x * y - r * z);
    float R02 = 2.0f * (x * z + r * y);
    float R10 = 2.0f * (x * y + r * z);
    float R11 = 1.0f - 2.0f * (x * x + z * z);
    float R12 = 2.0f * (y * z - r * x);
    float R20 = 2.0f * (x * z - r * y);
    float R21 = 2.0f * (y * z + r * x);
    float R22 = 1.0f - 2.0f * (x * x + y * y);

    float M00 = R00 * s0, M01 = R01 * s1, M02 = R02 * s2;
    float M10 = R10 * s0, M11 = R11 * s1, M12 = R12 * s2;
    float M20 = R20 * s0, M21 = R21 * s1, M22 = R22 * s2;

    cov00 = M00 * M00 + M01 * M01 + M02 * M02;
    cov01 = M00 * M10 + M01 * M11 + M02 * M12;
    cov02 = M00 * M20 + M01 * M21 + M02 * M22;
    cov11 = M10 * M10 + M11 * M11 + M12 * M12;
    cov12 = M10 * M20 + M11 * M21 + M12 * M22;
    cov22 = M20 * M20 + M21 * M21 + M22 * M22;
}

// Scalar per-point path (tail block / n%4!=0 fallback).
__device__ __forceinline__ void gauss_point_scalar(
    const float* __restrict__ view_dirs,
    const float* __restrict__ xyz,
    const float* __restrict__ scale_log,
    const float* __restrict__ rot_quat,
    const float* __restrict__ opacity_logit,
    const float* __restrict__ sh_coeffs,
    float* __restrict__ out,
    int i, int n)
{
    float dx = view_dirs[3 * i + 0], dy = view_dirs[3 * i + 1], dz = view_dirs[3 * i + 2];
    float px = xyz[3 * i + 0], py = xyz[3 * i + 1], pz = xyz[3 * i + 2];
    float sl0 = scale_log[3 * i + 0], sl1 = scale_log[3 * i + 1], sl2 = scale_log[3 * i + 2];
    float4 q  = reinterpret_cast<const float4*>(rot_quat)[i];
    float opl = opacity_logit[i];
    float4 c0 = reinterpret_cast<const float4*>(sh_coeffs)[3 * i + 0];
    float4 c1 = reinterpret_cast<const float4*>(sh_coeffs)[3 * i + 1];
    float4 c2 = reinterpret_cast<const float4*>(sh_coeffs)[3 * i + 2];

    float rr, rg, rb, opac, cov00, cov01, cov02, cov11, cov12, cov22;
    gauss_math(dx, dy, dz, sl0, sl1, sl2, q.x, q.y, q.z, q.w, opl,
               c0, c1, c2, rr, rg, rb, opac,
               cov00, cov01, cov02, cov11, cov12, cov22);

    float* o_xyz = out;
    float* o_cov = out + 3LL * n;
    float* o_rgb = out + 12LL * n;
    float* o_op  = out + 15LL * n;

    o_xyz[3 * i + 0] = px; o_xyz[3 * i + 1] = py; o_xyz[3 * i + 2] = pz;

    o_cov[9 * i + 0] = cov00; o_cov[9 * i + 1] = cov01; o_cov[9 * i + 2] = cov02;
    o_cov[9 * i + 3] = cov01; o_cov[9 * i + 4] = cov11; o_cov[9 * i + 5] = cov12;
    o_cov[9 * i + 6] = cov02; o_cov[9 * i + 7] = cov12; o_cov[9 * i + 8] = cov22;

    o_rgb[3 * i + 0] = rr; o_rgb[3 * i + 1] = rg; o_rgb[3 * i + 2] = rb;
    o_op[i] = opac;
}

// Fused kernel, lean smem transpose:
//   smem only for what actually needs transposition:
//     inputs:  VD f[0,768)  SL f[768,1536)  SH f[1536,4608)
//     outputs: COV f[4608,6912)  RGB f[6912,7680)     (separate region -> one less barrier)
//   direct global (already coalesced): quat, opacity in; xyz copy; opacity out.
__global__ void __launch_bounds__(NPB, 6) gaussian_kernel_fused(
    const float* __restrict__ view_dirs,
    const float* __restrict__ xyz,
    const float* __restrict__ scale_log,
    const float* __restrict__ rot_quat,
    const float* __restrict__ opacity_logit,
    const float* __restrict__ sh_coeffs,
    float* __restrict__ out,
    int n, int n_full_blocks)
{
    __shared__ float s[7680];
    float4* s4 = reinterpret_cast<float4*>(s);

    const int tid = threadIdx.x;
    const size_t b = blockIdx.x;

    if (blockIdx.x >= n_full_blocks) {
        int i = blockIdx.x * NPB + tid;
        if (i < n) {
            gauss_point_scalar(view_dirs, xyz, scale_log, rot_quat,
                               opacity_logit, sh_coeffs, out, i, n);
        }
        return;
    }

    const int i = (int)(b * NPB) + tid;

    // ---- direct coalesced accesses (no smem needed) ----
    float4 q  = reinterpret_cast<const float4*>(rot_quat)[i];
    float opl = opacity_logit[i];

    // xyz: pure identity copy, perfectly coalesced both sides
    if (tid < 192) {
        reinterpret_cast<float4*>(out)[b * 192 + tid] =
            reinterpret_cast<const float4*>(xyz)[b * 192 + tid];
    }

    // ---- stage transposition-needing inputs ----
    const float4* vd4 = reinterpret_cast<const float4*>(view_dirs) + b * 192;
    const float4* sl4 = reinterpret_cast<const float4*>(scale_log) + b * 192;
    const float4* sh4 = reinterpret_cast<const float4*>(sh_coeffs) + b * 768;

    if (tid < 192) {
        s4[0   + tid] = vd4[tid];
        s4[192 + tid] = sl4[tid];
    }
    s4[384 + tid]       = sh4[tid];
    s4[384 + 256 + tid] = sh4[256 + tid];
    s4[384 + 512 + tid] = sh4[512 + tid];
    __syncthreads();

    // ---- per-point reads (conflict-free: strides 3 and 48B-phase-distinct f4) ----
    const int p = tid;
    float dx  = s[3 * p + 0],       dy  = s[3 * p + 1],       dz  = s[3 * p + 2];
    float sl0 = s[768 + 3 * p],     sl1 = s[768 + 3 * p + 1], sl2 = s[768 + 3 * p + 2];
    float4 c0 = reinterpret_cast<const float4*>(s + 1536)[3 * p + 0];
    float4 c1 = reinterpret_cast<const float4*>(s + 1536)[3 * p + 1];
    float4 c2 = reinterpret_cast<const float4*>(s + 1536)[3 * p + 2];

    float rr, rg, rb, opac, cov00, cov01, cov02, cov11, cov12, cov22;
    gauss_math(dx, dy, dz, sl0, sl1, sl2, q.x, q.y, q.z, q.w, opl,
               c0, c1, c2, rr, rg, rb, opac,
               cov00, cov01, cov02, cov11, cov12, cov22);

    // opacity out: direct coalesced scalar store
    (out + 15LL * n)[i] = opac;

    // ---- outputs into separate smem region (no barrier needed before writes) ----
    float* sc = s + 4608 + 9 * p;
    sc[0] = cov00; sc[1] = cov01; sc[2] = cov02;
    sc[3] = cov01; sc[4] = cov11; sc[5] = cov12;
    sc[6] = cov02; sc[7] = cov12; sc[8] = cov22;

    s[6912 + 3 * p + 0] = rr; s[6912 + 3 * p + 1] = rg; s[6912 + 3 * p + 2] = rb;
    __syncthreads();

    // ---- flush: coalesced float4 stores ----
    float4* ocov4 = reinterpret_cast<float4*>(out + 3LL * n)  + b * 576;
    float4* orgb4 = reinterpret_cast<float4*>(out + 12LL * n) + b * 192;

    ocov4[tid]       = s4[1152 + tid];
    ocov4[256 + tid] = s4[1408 + tid];
    if (tid < 64) {
        ocov4[512 + tid] = s4[1664 + tid];
    }
    if (tid < 192) {
        orgb4[tid] = s4[1728 + tid];
    }
}

// Pure scalar kernel for the n % 4 != 0 fallback.
__global__ void __launch_bounds__(256) gaussian_kernel_scalar(
    const float* __restrict__ view_dirs,
    const float* __restrict__ xyz,
    const float* __restrict__ scale_log,
    const float* __restrict__ rot_quat,
    const float* __restrict__ opacity_logit,
    const float* __restrict__ sh_coeffs,
    float* __restrict__ out,
    int n)
{
    int i = blockIdx.x * blockDim.x + threadIdx.x;
    if (i >= n) return;
    gauss_point_scalar(view_dirs, xyz, scale_log, rot_quat,
                       opacity_logit, sh_coeffs, out, i, n);
}

extern "C" void kernel_launch(void* const* d_in, const int* in_sizes, int n_in,
                              void* d_out, int out_size) {
    const float* view_dirs     = (const float*)d_in[0];
    const float* xyz           = (const float*)d_in[1];
    const float* scale_log     = (const float*)d_in[2];
    const float* rot_quat      = (const float*)d_in[3];
    const float* opacity_logit = (const float*)d_in[4];
    const float* sh_coeffs     = (const float*)d_in[5];
    float* out = (float*)d_out;

    int n = in_sizes[0] / 3;

    if ((n & 3) != 0) {
        int threads = 256;
        int blocks = (n + threads - 1) / threads;
        gaussian_kernel_scalar<<<blocks, threads>>>(view_dirs, xyz, scale_log, rot_quat,
                                                    opacity_logit, sh_coeffs, out, n);
        return;
    }

    int n_full_blocks = n / NPB;
    int grid = (n + NPB - 1) / NPB;

    gaussian_kernel_fused<<<grid, NPB>>>(view_dirs, xyz, scale_log, rot_quat,
                                         opacity_logit, sh_coeffs, out,
                                         n, n_full_blocks);
}